// round 3
// baseline (speedup 1.0000x reference)
#include <cuda_runtime.h>
#include <math.h>

#define B_    8
#define CF_   64
#define HW_   65536
#define HID_  512
#define K_    64
#define TILE_P 64
#define CHUNK  64
#define NCHUNK (HID_ / CHUNK)
#define PAD   4
#define ROW   (TILE_P + PAD)   // 68 floats per smem row

// ---- scratch (device globals; no runtime allocation) ----
__device__ float g_mask[(size_t)B_ * K_ * HW_];   // 134 MB softmax output
__device__ float g_wc[B_ * 3 * K_];               // weighted_color accumulator
__device__ float g_ksum[B_ * K_];                 // sum of mask over hw
__device__ float g_kmax[B_ * K_];                 // max of mask over hw

// ---------------------------------------------------------------------------
// Kernel 0: zero the accumulators (mask values are >0 so kmax init 0 is safe)
// ---------------------------------------------------------------------------
__global__ void k0_init() {
    int i = blockIdx.x * blockDim.x + threadIdx.x;
    if (i < B_ * 3 * K_) g_wc[i] = 0.f;
    if (i < B_ * K_) { g_ksum[i] = 0.f; g_kmax[i] = 0.f; }
}

// ---------------------------------------------------------------------------
// Kernel 1: per 64-pixel tile -> fused GEMM1 + relu + GEMM2 + softmax,
// write mask, accumulate wc / ksum / kmax.
// 256 threads = 16(tx: k / dd dim) x 16(ty: pixel dim), 4x4 register tiles.
// ---------------------------------------------------------------------------
__global__ __launch_bounds__(256, 2)
void k1_mask(const float* __restrict__ feat, const float* __restrict__ img,
             const float* __restrict__ w1,  const float* __restrict__ b1,
             const float* __restrict__ w2,  const float* __restrict__ b2)
{
    extern __shared__ float smem[];
    float (*feat_s)[ROW] = (float(*)[ROW])(smem);                 // [CF][p]
    float (*w1_s)[ROW]   = (float(*)[ROW])(smem + 1 * 64 * ROW);  // [c][dd]
    float (*w2_s)[ROW]   = (float(*)[ROW])(smem + 2 * 64 * ROW);  // [dd][k]
    float (*h_s)[ROW]    = (float(*)[ROW])(smem + 3 * 64 * ROW);  // [dd][p] / mask[k][p]
    float *img_s         = smem + 4 * 64 * ROW;                   // [3*TILE_P]

    const int t  = threadIdx.x;
    const int tx = t & 15, ty = t >> 4;
    const int b    = blockIdx.x >> 10;           // 1024 tiles per batch
    const int base = (blockIdx.x & 1023) * TILE_P;

    // load feat tile (coalesced float4)
    #pragma unroll
    for (int i = 0; i < 4; i++) {
        int v = t + i * 256; int c = v >> 4, seg = v & 15;
        float4 d = *(reinterpret_cast<const float4*>(
                        feat + ((size_t)(b * CF_ + c)) * HW_ + base) + seg);
        *reinterpret_cast<float4*>(&feat_s[c][seg * 4]) = d;
    }
    if (t < 48) {
        int c = t >> 4, seg = t & 15;
        float4 d = *(reinterpret_cast<const float4*>(
                        img + ((size_t)(b * 3 + c)) * HW_ + base) + seg);
        *reinterpret_cast<float4*>(&img_s[c * TILE_P + seg * 4]) = d;
    }

    float lg[4][4];   // logits[p_local][k_local]
    #pragma unroll
    for (int i = 0; i < 4; i++)
        #pragma unroll
        for (int j = 0; j < 4; j++) lg[i][j] = 0.f;

    for (int ch = 0; ch < NCHUNK; ch++) {
        const int d0 = ch * CHUNK;
        __syncthreads();   // previous chunk fully consumed
        #pragma unroll
        for (int i = 0; i < 4; i++) {
            int v = t + i * 256; int r = v >> 4, seg = v & 15;
            *reinterpret_cast<float4*>(&w1_s[r][seg * 4]) =
                *(reinterpret_cast<const float4*>(w1 + (size_t)r * HID_ + d0) + seg);
            *reinterpret_cast<float4*>(&w2_s[r][seg * 4]) =
                *(reinterpret_cast<const float4*>(w2 + (size_t)(d0 + r) * K_) + seg);
        }
        __syncthreads();

        // GEMM1: h[dd][p] for dd = tx*4.., p = ty*4..
        float acc[4][4];   // [dd_local][p_local]
        #pragma unroll
        for (int j = 0; j < 4; j++) {
            float bv = __ldg(&b1[d0 + tx * 4 + j]);
            #pragma unroll
            for (int i = 0; i < 4; i++) acc[j][i] = bv;
        }
        #pragma unroll 4
        for (int c = 0; c < CF_; c++) {
            float4 fv = *reinterpret_cast<float4*>(&feat_s[c][ty * 4]);
            float4 wv = *reinterpret_cast<float4*>(&w1_s[c][tx * 4]);
            float f[4] = {fv.x, fv.y, fv.z, fv.w};
            float w[4] = {wv.x, wv.y, wv.z, wv.w};
            #pragma unroll
            for (int j = 0; j < 4; j++)
                #pragma unroll
                for (int i = 0; i < 4; i++)
                    acc[j][i] = fmaf(w[j], f[i], acc[j][i]);
        }
        #pragma unroll
        for (int j = 0; j < 4; j++)
            #pragma unroll
            for (int i = 0; i < 4; i++)
                h_s[tx * 4 + j][ty * 4 + i] = fmaxf(acc[j][i], 0.f);
        __syncthreads();

        // GEMM2: logits += h * w2 over this chunk
        #pragma unroll 4
        for (int dd = 0; dd < CHUNK; dd++) {
            float4 hv = *reinterpret_cast<float4*>(&h_s[dd][ty * 4]);
            float4 wv = *reinterpret_cast<float4*>(&w2_s[dd][tx * 4]);
            float h4[4] = {hv.x, hv.y, hv.z, hv.w};
            float w4[4] = {wv.x, wv.y, wv.z, wv.w};
            #pragma unroll
            for (int i = 0; i < 4; i++)
                #pragma unroll
                for (int j = 0; j < 4; j++)
                    lg[i][j] = fmaf(h4[i], w4[j], lg[i][j]);
        }
    }
    #pragma unroll
    for (int j = 0; j < 4; j++) {
        float bv = __ldg(&b2[tx * 4 + j]);
        #pragma unroll
        for (int i = 0; i < 4; i++) lg[i][j] += bv;
    }

    // softmax over k: 64 k-values live on 16 tx lanes (4 each).
    // xor offsets 1/2/4/8 stay inside the 16-lane tx group of each half-warp.
    #pragma unroll
    for (int i = 0; i < 4; i++) {
        float m = fmaxf(fmaxf(lg[i][0], lg[i][1]), fmaxf(lg[i][2], lg[i][3]));
        #pragma unroll
        for (int off = 1; off < 16; off <<= 1)
            m = fmaxf(m, __shfl_xor_sync(0xffffffffu, m, off));
        float s = 0.f;
        #pragma unroll
        for (int j = 0; j < 4; j++) { lg[i][j] = expf(lg[i][j] - m); s += lg[i][j]; }
        #pragma unroll
        for (int off = 1; off < 16; off <<= 1)
            s += __shfl_xor_sync(0xffffffffu, s, off);
        float inv = 1.f / s;
        #pragma unroll
        for (int j = 0; j < 4; j++) lg[i][j] *= inv;
    }

    // stage mask[k][p] in h_s (done with it), then tile-level outputs
    __syncthreads();
    #pragma unroll
    for (int j = 0; j < 4; j++)
        #pragma unroll
        for (int i = 0; i < 4; i++)
            h_s[tx * 4 + j][ty * 4 + i] = lg[i][j];
    __syncthreads();

    // coalesced global mask write
    {
        int k = t >> 2, seg = t & 3;
        float* dst = g_mask + ((size_t)(b * K_ + k)) * HW_ + base + seg * 16;
        #pragma unroll
        for (int q = 0; q < 4; q++)
            reinterpret_cast<float4*>(dst)[q] =
                *reinterpret_cast<float4*>(&h_s[k][seg * 16 + q * 4]);
    }
    // weighted_color partials: one (c,k) pair per thread
    if (t < 192) {
        int c = t >> 6, k = t & 63;
        float s = 0.f;
        #pragma unroll 8
        for (int p = 0; p < TILE_P; p++)
            s = fmaf(img_s[c * TILE_P + p], h_s[k][p], s);
        atomicAdd(&g_wc[(b * 3 + c) * K_ + k], s);
    }
    // per-k sum and max over this tile's pixels
    if (t < 64) {
        float s = 0.f, m = 0.f;
        #pragma unroll 8
        for (int p = 0; p < TILE_P; p++) {
            float v = h_s[t][p]; s += v; m = fmaxf(m, v);
        }
        atomicAdd(&g_ksum[b * K_ + t], s);
        atomicMax(reinterpret_cast<int*>(&g_kmax[b * K_ + t]), __float_as_int(m));
    }
}

// ---------------------------------------------------------------------------
// Kernel 2: finalize wc (/HW) and the two scalars
// ---------------------------------------------------------------------------
__global__ void k2_finalize(float* __restrict__ out, int out_size) {
    __shared__ float mu[B_ * K_];
    __shared__ float red[512];
    __shared__ float stds[B_];
    int t = threadIdx.x;   // 512 threads
    for (int i = t; i < B_ * 3 * K_; i += 512) g_wc[i] *= (1.0f / HW_);
    mu[t]  = g_ksum[t] * (1.0f / HW_);
    red[t] = g_kmax[t];
    __syncthreads();
    for (int s = 256; s > 0; s >>= 1) {
        if (t < s) red[t] += red[t + s];
        __syncthreads();
    }
    if (t < B_) {
        float m = 0.f;
        for (int k = 0; k < K_; k++) m += mu[t * K_ + k];
        m *= (1.0f / K_);
        float v = 0.f;
        for (int k = 0; k < K_; k++) { float d = mu[t * K_ + k] - m; v += d * d; }
        stds[t] = sqrtf(v / (K_ - 1));   // ddof=1
    }
    __syncthreads();
    if (t == 0) {
        float sm = 0.f;
        for (int b = 0; b < B_; b++) sm += stds[b];
        out[out_size - 2] = red[0] / (B_ * K_);   // mean_max
        out[out_size - 1] = sm / B_;              // std_mean
    }
}

// ---------------------------------------------------------------------------
// Kernel 3: transformed_img[b,c,p] = sum_k mask[b,k,p] * wc[b,c,k]
// ---------------------------------------------------------------------------
__global__ __launch_bounds__(256)
void k3_transform(float* __restrict__ out) {
    __shared__ float wc_s[3 * K_];
    int b = blockIdx.y;
    int p = blockIdx.x * 256 + threadIdx.x;
    if (threadIdx.x < 192) wc_s[threadIdx.x] = g_wc[b * 192 + threadIdx.x];
    __syncthreads();
    const float* mp = g_mask + (size_t)b * K_ * HW_ + p;
    float a0 = 0.f, a1 = 0.f, a2 = 0.f;
    #pragma unroll 8
    for (int k = 0; k < K_; k++) {
        float m = mp[(size_t)k * HW_];
        a0 = fmaf(m, wc_s[k],           a0);
        a1 = fmaf(m, wc_s[K_ + k],      a1);
        a2 = fmaf(m, wc_s[2 * K_ + k],  a2);
    }
    out[((size_t)b * 3 + 0) * HW_ + p] = a0;
    out[((size_t)b * 3 + 1) * HW_ + p] = a1;
    out[((size_t)b * 3 + 2) * HW_ + p] = a2;
}

// ---------------------------------------------------------------------------
// Host launcher (graph-capturable: kernel launches only)
// ---------------------------------------------------------------------------
extern "C" void kernel_launch(void* const* d_in, const int* in_sizes, int n_in,
                              void* d_out, int out_size) {
    (void)in_sizes; (void)n_in;
    const float* img  = (const float*)d_in[0];
    const float* feat = (const float*)d_in[1];
    // d_in[2] = coord_map (unused by the reference computation)
    const float* w1   = (const float*)d_in[3];
    const float* b1   = (const float*)d_in[4];
    const float* w2   = (const float*)d_in[5];
    const float* b2   = (const float*)d_in[6];
    float* out = (float*)d_out;

    const int smem_bytes = (4 * 64 * ROW + 3 * TILE_P) * (int)sizeof(float); // 70400
    cudaFuncSetAttribute(k1_mask, cudaFuncAttributeMaxDynamicSharedMemorySize, smem_bytes);

    k0_init<<<3, 512>>>();
    k1_mask<<<B_ * (HW_ / TILE_P), 256, smem_bytes>>>(feat, img, w1, b1, w2, b2);
    k2_finalize<<<1, 512>>>(out, out_size);
    k3_transform<<<dim3(HW_ / 256, B_), 256>>>(out);
}

// round 5
// speedup vs baseline: 2.6082x; 2.6082x over previous
#include <cuda_runtime.h>
#include <cuda_bf16.h>
#include <math.h>
#include <stdint.h>

#define B_    8
#define CF_   64
#define HW_   65536
#define HID_  512
#define K_    64
#define TILE_P 128
#define NCHUNK 4          // hid chunks of 128

// ============================ device scratch ================================
__device__ float g_mask[(size_t)B_ * K_ * HW_];
__device__ float g_wc[B_ * 3 * K_];
__device__ float g_ksum[B_ * K_];
__device__ float g_kmax[B_ * K_];
__device__ __nv_bfloat16 g_featT_hi[(size_t)B_ * HW_ * CF_];  // [b][hw][c]
__device__ __nv_bfloat16 g_featT_lo[(size_t)B_ * HW_ * CF_];
__device__ __nv_bfloat16 g_w1t_hi[HID_ * CF_];                // [hid][c]
__device__ __nv_bfloat16 g_w1t_lo[HID_ * CF_];
__device__ __nv_bfloat16 g_w2t_hi[K_ * HID_];                 // [k][hid]
__device__ __nv_bfloat16 g_w2t_lo[K_ * HID_];

// ============================ helpers =======================================
__device__ __forceinline__ uint32_t smem_u32(const void* p) {
    uint32_t a;
    asm("{ .reg .u64 t; cvta.to.shared.u64 t, %1; cvt.u32.u64 %0, t; }" : "=r"(a) : "l"(p));
    return a;
}
__device__ __forceinline__ unsigned short bfu(float x) { return __bfloat16_as_ushort(__float2bfloat16_rn(x)); }
__device__ __forceinline__ float bff(unsigned short u) { return __bfloat162float(__ushort_as_bfloat16(u)); }

#define LDSM4(r0, r1, r2, r3, a) \
    asm volatile("ldmatrix.sync.aligned.m8n8.x4.shared.b16 {%0,%1,%2,%3}, [%4];" \
        : "=r"(r0), "=r"(r1), "=r"(r2), "=r"(r3) : "r"(a))

#define MMA_BF16(c, a, b0_, b1_) \
    asm volatile("mma.sync.aligned.m16n8k16.row.col.f32.bf16.bf16.f32 " \
        "{%0,%1,%2,%3}, {%4,%5,%6,%7}, {%8,%9}, {%0,%1,%2,%3};" \
        : "+f"((c)[0]), "+f"((c)[1]), "+f"((c)[2]), "+f"((c)[3]) \
        : "r"((a)[0]), "r"((a)[1]), "r"((a)[2]), "r"((a)[3]), "r"(b0_), "r"(b1_))

// d = {upper=bf16(vh), lower=bf16(vl)}
#define CVT_PACK(d, vh, vl) \
    asm("cvt.rn.bf16x2.f32 %0, %1, %2;" : "=r"(d) : "f"(vh), "f"(vl))

// SMEM layout (bytes). Row padding +16B kills ldmatrix bank conflicts.
#define SA1HI 0          // 128 x (128B payload, 144B stride)
#define SA1LO 18432
#define SW1HI 36864      // 128 x 144
#define SW1LO 55296
#define SW2HI 73728      // 64 x (256B payload, 272B stride)
#define SW2LO 91136
#define SIMG  108544     // 3*128 floats
#define SMEM_K1 110592
// mask staging reuses [0 .. 64*132*4) = A1 region (dead by then), stride 132 floats

// ============================ prep kernels ==================================
__global__ __launch_bounds__(256) void k_prep_feat(const float* __restrict__ feat) {
    __shared__ float ts[64][65];
    const int t = threadIdx.x;
    const int b = blockIdx.x >> 10;
    const int p0 = (blockIdx.x & 1023) << 6;
    #pragma unroll
    for (int i = 0; i < 4; i++) {
        int v = t + i * 256, c = v >> 4, sg = v & 15;
        float4 f = ((const float4*)(feat + (size_t)(b * CF_ + c) * HW_ + p0))[sg];
        ts[sg * 4 + 0][c] = f.x; ts[sg * 4 + 1][c] = f.y;
        ts[sg * 4 + 2][c] = f.z; ts[sg * 4 + 3][c] = f.w;
    }
    __syncthreads();
    const int p = t >> 2, q = t & 3, c0 = q * 16;
    uint32_t hi[8], lo[8];
    #pragma unroll
    for (int j = 0; j < 8; j++) {
        float x0 = ts[p][c0 + 2 * j], x1 = ts[p][c0 + 2 * j + 1];
        unsigned short a0 = bfu(x0), a1 = bfu(x1);
        hi[j] = (uint32_t)a0 | ((uint32_t)a1 << 16);
        float l0 = x0 - bff(a0), l1 = x1 - bff(a1);
        lo[j] = (uint32_t)bfu(l0) | ((uint32_t)bfu(l1) << 16);
    }
    size_t rb = ((size_t)b * HW_ + p0 + p) * CF_ + c0;
    ((uint4*)(g_featT_hi + rb))[0] = make_uint4(hi[0], hi[1], hi[2], hi[3]);
    ((uint4*)(g_featT_hi + rb))[1] = make_uint4(hi[4], hi[5], hi[6], hi[7]);
    ((uint4*)(g_featT_lo + rb))[0] = make_uint4(lo[0], lo[1], lo[2], lo[3]);
    ((uint4*)(g_featT_lo + rb))[1] = make_uint4(lo[4], lo[5], lo[6], lo[7]);
}

__global__ __launch_bounds__(256) void k_prep_w(const float* __restrict__ w1,
                                                const float* __restrict__ w2) {
    int t0 = blockIdx.x * 256 + threadIdx.x;
    int stride = gridDim.x * 256;
    for (int idx = t0; idx < HID_ * CF_; idx += stride) {   // w1t[hid][c] = w1[c][hid]
        int c = idx & 63, hid = idx >> 6;
        float x = w1[c * HID_ + hid];
        unsigned short h = bfu(x);
        g_w1t_hi[idx] = __ushort_as_bfloat16(h);
        g_w1t_lo[idx] = __float2bfloat16_rn(x - bff(h));
    }
    for (int idx = t0; idx < K_ * HID_; idx += stride) {    // w2t[k][hid] = w2[hid][k]
        int hid = idx & 511, k = idx >> 9;
        float x = w2[hid * K_ + k];
        unsigned short h = bfu(x);
        g_w2t_hi[idx] = __ushort_as_bfloat16(h);
        g_w2t_lo[idx] = __float2bfloat16_rn(x - bff(h));
    }
}

__global__ void k0_init() {
    int i = blockIdx.x * blockDim.x + threadIdx.x;
    if (i < B_ * 3 * K_) g_wc[i] = 0.f;
    if (i < B_ * K_) { g_ksum[i] = 0.f; g_kmax[i] = 0.f; }
}

// ============================ main fused kernel =============================
__global__ __launch_bounds__(256, 1)
void k1_mask(const float* __restrict__ img,
             const float* __restrict__ b1, const float* __restrict__ b2)
{
    extern __shared__ char smem[];
    const uint32_t sb = smem_u32(smem);
    const int t = threadIdx.x;
    const int lane = t & 31, w = t >> 5;
    const int q = lane & 3;
    const int b = blockIdx.x >> 9;
    const int base = (blockIdx.x & 511) * TILE_P;

    // ---- load A1 (feat hi/lo, 128 rows x 128B, stride 144) + img ----
    #pragma unroll
    for (int j = 0; j < 4; j++) {
        int i = t + j * 256, row = i >> 3, seg = i & 7;
        const size_t src = ((size_t)b * HW_ + base + row) * CF_ + seg * 8;
        *(uint4*)(smem + SA1HI + row * 144 + seg * 16) = *(const uint4*)(g_featT_hi + src);
        *(uint4*)(smem + SA1LO + row * 144 + seg * 16) = *(const uint4*)(g_featT_lo + src);
    }
    if (t < 96) {
        int c = t >> 5, sg = t & 31;
        float4 v = ((const float4*)(img + (size_t)(b * 3 + c) * HW_ + base))[sg];
        *(float4*)(smem + SIMG + (c * 128 + sg * 4) * 4) = v;
    }
    __syncthreads();

    // ---- A1 fragments (held for all chunks): warp rows 16w..16w+15 ----
    const int rowA = 16 * w + (lane & 15);
    const int khA = lane >> 4;
    uint32_t a1hi[4][4], a1lo[4][4];
    #pragma unroll
    for (int ks = 0; ks < 4; ks++) {
        LDSM4(a1hi[ks][0], a1hi[ks][1], a1hi[ks][2], a1hi[ks][3],
              sb + SA1HI + rowA * 144 + ks * 32 + khA * 16);
        LDSM4(a1lo[ks][0], a1lo[ks][1], a1lo[ks][2], a1lo[ks][3],
              sb + SA1LO + rowA * 144 + ks * 32 + khA * 16);
    }

    // B-fragment lane addressing (shared by W1/W2)
    const int rowB = ((lane >> 4) << 3) + (lane & 7);
    const int khB = (lane >> 3) & 1;

    float c2[8][4];
    #pragma unroll
    for (int nb = 0; nb < 8; nb++)
        #pragma unroll
        for (int j = 0; j < 4; j++) c2[nb][j] = 0.f;

    for (int ch = 0; ch < NCHUNK; ch++) {
        const int d0 = ch * 128;
        __syncthreads();   // previous chunk's weight reads done
        #pragma unroll
        for (int j = 0; j < 4; j++) {
            int i = t + j * 256;
            { int row = i >> 3, seg = i & 7;
              const size_t s = (size_t)(d0 + row) * CF_ + seg * 8;
              *(uint4*)(smem + SW1HI + row * 144 + seg * 16) = *(const uint4*)(g_w1t_hi + s);
              *(uint4*)(smem + SW1LO + row * 144 + seg * 16) = *(const uint4*)(g_w1t_lo + s); }
            { int row = i >> 4, seg = i & 15;
              const size_t s = (size_t)row * HID_ + d0 + seg * 8;
              *(uint4*)(smem + SW2HI + row * 272 + seg * 16) = *(const uint4*)(g_w2t_hi + s);
              *(uint4*)(smem + SW2LO + row * 272 + seg * 16) = *(const uint4*)(g_w2t_lo + s); }
        }
        __syncthreads();

        // ---- GEMM1: c1[128 x 128hid], bias-initialized ----
        float c1[16][4];
        #pragma unroll
        for (int nb = 0; nb < 16; nb++) {
            float bv0 = __ldg(&b1[d0 + 8 * nb + 2 * q]);
            float bv1 = __ldg(&b1[d0 + 8 * nb + 2 * q + 1]);
            c1[nb][0] = bv0; c1[nb][1] = bv1; c1[nb][2] = bv0; c1[nb][3] = bv1;
        }
        #pragma unroll
        for (int nbp = 0; nbp < 8; nbp++) {
            uint32_t bH = sb + SW1HI + (16 * nbp + rowB) * 144 + khB * 16;
            uint32_t bL = sb + SW1LO + (16 * nbp + rowB) * 144 + khB * 16;
            #pragma unroll
            for (int k = 0; k < 4; k++) {
                uint32_t h0, h1, h2, h3, l0, l1, l2, l3;
                LDSM4(h0, h1, h2, h3, bH + k * 32);
                LDSM4(l0, l1, l2, l3, bL + k * 32);
                MMA_BF16(c1[2 * nbp],     a1hi[k], h0, h1);   // hi*hi
                MMA_BF16(c1[2 * nbp + 1], a1hi[k], h2, h3);
                MMA_BF16(c1[2 * nbp],     a1hi[k], l0, l1);   // hi*lo
                MMA_BF16(c1[2 * nbp + 1], a1hi[k], l2, l3);
                MMA_BF16(c1[2 * nbp],     a1lo[k], h0, h1);   // lo*hi
                MMA_BF16(c1[2 * nbp + 1], a1lo[k], h2, h3);
            }
        }

        // ---- epilogue: relu -> bf16 hi/lo packed straight into GEMM2 A frags ----
        uint32_t ahi[8][4], alo[8][4];
        #pragma unroll
        for (int ks = 0; ks < 8; ks++) {
            #pragma unroll
            for (int ai = 0; ai < 4; ai++) {
                const int nb = 2 * ks + (ai >> 1);
                const int j0 = (ai & 1) * 2;
                float v0 = fmaxf(c1[nb][j0], 0.f);
                float v1 = fmaxf(c1[nb][j0 + 1], 0.f);
                uint32_t hp; CVT_PACK(hp, v1, v0);
                float r0 = v0 - __uint_as_float(hp << 16);
                float r1 = v1 - __uint_as_float(hp & 0xffff0000u);
                uint32_t lp; CVT_PACK(lp, r1, r0);
                ahi[ks][ai] = hp; alo[ks][ai] = lp;
            }
        }

        // ---- GEMM2: c2[128 x 64] += h * w2^T ----
        #pragma unroll
        for (int np = 0; np < 4; np++) {
            uint32_t bH = sb + SW2HI + (16 * np + rowB) * 272 + khB * 16;
            uint32_t bL = sb + SW2LO + (16 * np + rowB) * 272 + khB * 16;
            #pragma unroll
            for (int ks = 0; ks < 8; ks++) {
                uint32_t h0, h1, h2, h3, l0, l1, l2, l3;
                LDSM4(h0, h1, h2, h3, bH + ks * 32);
                LDSM4(l0, l1, l2, l3, bL + ks * 32);
                MMA_BF16(c2[2 * np],     ahi[ks], h0, h1);
                MMA_BF16(c2[2 * np + 1], ahi[ks], h2, h3);
                MMA_BF16(c2[2 * np],     ahi[ks], l0, l1);
                MMA_BF16(c2[2 * np + 1], ahi[ks], l2, l3);
                MMA_BF16(c2[2 * np],     alo[ks], h0, h1);
                MMA_BF16(c2[2 * np + 1], alo[ks], h2, h3);
            }
        }
    }

    // ---- softmax over K=64 per pixel ----
    // thread holds rows (16w + lane/4) and (+8); cols {8nb+2q, 8nb+2q+1 : nb<8}
    #pragma unroll
    for (int nb = 0; nb < 8; nb++) {
        float bv0 = __ldg(&b2[8 * nb + 2 * q]);
        float bv1 = __ldg(&b2[8 * nb + 2 * q + 1]);
        c2[nb][0] += bv0; c2[nb][1] += bv1; c2[nb][2] += bv0; c2[nb][3] += bv1;
    }
    float* mask_s = (float*)smem;             // [64][132]
    const int r0g = 16 * w + (lane >> 2);
    #pragma unroll
    for (int half = 0; half < 2; half++) {    // j-pair {0,1} row r, {2,3} row r+8
        const int j0 = half * 2;
        float m = -1e30f;
        #pragma unroll
        for (int nb = 0; nb < 8; nb++) m = fmaxf(m, fmaxf(c2[nb][j0], c2[nb][j0 + 1]));
        m = fmaxf(m, __shfl_xor_sync(0xffffffffu, m, 1));
        m = fmaxf(m, __shfl_xor_sync(0xffffffffu, m, 2));
        float s = 0.f;
        #pragma unroll
        for (int nb = 0; nb < 8; nb++) {
            c2[nb][j0]     = expf(c2[nb][j0] - m);
            c2[nb][j0 + 1] = expf(c2[nb][j0 + 1] - m);
            s += c2[nb][j0] + c2[nb][j0 + 1];
        }
        s += __shfl_xor_sync(0xffffffffu, s, 1);
        s += __shfl_xor_sync(0xffffffffu, s, 2);
        float inv = 1.f / s;
        const int p = r0g + half * 8;
        #pragma unroll
        for (int nb = 0; nb < 8; nb++) {
            mask_s[(8 * nb + 2 * q)     * 132 + p] = c2[nb][j0] * inv;
            mask_s[(8 * nb + 2 * q + 1) * 132 + p] = c2[nb][j0 + 1] * inv;
        }
    }
    __syncthreads();

    // ---- outputs ----
    float* img_s = (float*)(smem + SIMG);
    {
        int k = t >> 2, sg = t & 3;
        float4* dst = (float4*)(g_mask + ((size_t)(b * K_ + k)) * HW_ + base);
        #pragma unroll
        for (int qq = 0; qq < 8; qq++)
            dst[sg * 8 + qq] = *(float4*)&mask_s[k * 132 + sg * 32 + qq * 4];
    }
    if (t < 192) {
        int c = t >> 6, k = t & 63;
        float s = 0.f;
        #pragma unroll 16
        for (int p = 0; p < TILE_P; p++)
            s = fmaf(img_s[c * 128 + p], mask_s[k * 132 + p], s);
        atomicAdd(&g_wc[(b * 3 + c) * K_ + k], s);
    }
    if (t < 64) {
        float s = 0.f, m = 0.f;
        #pragma unroll 16
        for (int p = 0; p < TILE_P; p++) {
            float v = mask_s[t * 132 + p]; s += v; m = fmaxf(m, v);
        }
        atomicAdd(&g_ksum[b * K_ + t], s);
        atomicMax((int*)&g_kmax[b * K_ + t], __float_as_int(m));
    }
}

// ============================ finalize + transform ==========================
__global__ void k2_finalize(float* __restrict__ out, int out_size) {
    __shared__ float mu[B_ * K_];
    __shared__ float red[512];
    __shared__ float stds[B_];
    int t = threadIdx.x;
    for (int i = t; i < B_ * 3 * K_; i += 512) g_wc[i] *= (1.0f / HW_);
    mu[t]  = g_ksum[t] * (1.0f / HW_);
    red[t] = g_kmax[t];
    __syncthreads();
    for (int s = 256; s > 0; s >>= 1) {
        if (t < s) red[t] += red[t + s];
        __syncthreads();
    }
    if (t < B_) {
        float m = 0.f;
        for (int k = 0; k < K_; k++) m += mu[t * K_ + k];
        m *= (1.0f / K_);
        float v = 0.f;
        for (int k = 0; k < K_; k++) { float d = mu[t * K_ + k] - m; v += d * d; }
        stds[t] = sqrtf(v / (K_ - 1));
    }
    __syncthreads();
    if (t == 0) {
        float sm = 0.f;
        for (int bb = 0; bb < B_; bb++) sm += stds[bb];
        out[out_size - 2] = red[0] / (B_ * K_);
        out[out_size - 1] = sm / B_;
    }
}

__global__ __launch_bounds__(256)
void k3_transform(float* __restrict__ out) {
    __shared__ float wc_s[3 * K_];
    int b = blockIdx.y;
    int p = blockIdx.x * 256 + threadIdx.x;
    if (threadIdx.x < 192) wc_s[threadIdx.x] = g_wc[b * 192 + threadIdx.x];
    __syncthreads();
    const float* mp = g_mask + (size_t)b * K_ * HW_ + p;
    float a0 = 0.f, a1 = 0.f, a2 = 0.f;
    #pragma unroll 8
    for (int k = 0; k < K_; k++) {
        float m = mp[(size_t)k * HW_];
        a0 = fmaf(m, wc_s[k],          a0);
        a1 = fmaf(m, wc_s[K_ + k],     a1);
        a2 = fmaf(m, wc_s[2 * K_ + k], a2);
    }
    out[((size_t)b * 3 + 0) * HW_ + p] = a0;
    out[((size_t)b * 3 + 1) * HW_ + p] = a1;
    out[((size_t)b * 3 + 2) * HW_ + p] = a2;
}

// ============================ launcher ======================================
extern "C" void kernel_launch(void* const* d_in, const int* in_sizes, int n_in,
                              void* d_out, int out_size) {
    (void)in_sizes; (void)n_in;
    const float* img  = (const float*)d_in[0];
    const float* feat = (const float*)d_in[1];
    const float* w1   = (const float*)d_in[3];
    const float* b1   = (const float*)d_in[4];
    const float* w2   = (const float*)d_in[5];
    const float* b2   = (const float*)d_in[6];
    float* out = (float*)d_out;

    cudaFuncSetAttribute(k1_mask, cudaFuncAttributeMaxDynamicSharedMemorySize, SMEM_K1);

    k_prep_w<<<64, 256>>>(w1, w2);
    k_prep_feat<<<B_ * (HW_ / 64), 256>>>(feat);
    k0_init<<<3, 512>>>();
    k1_mask<<<B_ * (HW_ / TILE_P), 256, SMEM_K1>>>(img, b1, b2);
    k2_finalize<<<1, 512>>>(out, out_size);
    k3_transform<<<dim3(HW_ / 256, B_), 256>>>(out);
}